// round 11
// baseline (speedup 1.0000x reference)
#include <cuda_runtime.h>
#include <cstdint>

#define B_  4
#define T_  2048
#define C_  1024
#define H_  16
#define HD_ 64
#define M_  (B_ * T_)     // 8192
#define N1  (3 * C_)      // 3072
#define PERSIST_GRID 296  // 2 CTAs x 148 SMs

// Scratch (__device__ globals per allocation rules)
__device__ float g_qkv[(size_t)M_ * N1];        // 96 MB (tf32-rounded by gemm epilogue)
__device__ float g_att[(size_t)M_ * C_];        // 32 MB (tf32-rounded by flash epilogue)
__device__ float g_xr [(size_t)M_ * C_];        // 32 MB (tf32-rounded x)
__device__ float g_wt1[(size_t)N1 * C_];        // 12 MB (Wqkv^T, rounded)
__device__ float g_wt2[(size_t)C_ * C_];        //  4 MB (Wout^T, rounded)

// ---------------------------------------------------------------------------
// helpers
// ---------------------------------------------------------------------------
__device__ __forceinline__ uint32_t smem_u32(const void* p) {
    uint32_t a;
    asm("{ .reg .u64 t; cvta.to.shared.u64 t, %1; cvt.u32.u64 %0, t; }"
        : "=r"(a) : "l"(p));
    return a;
}
__device__ __forceinline__ void cp16(uint32_t dst, const void* src) {
    asm volatile("cp.async.cg.shared.global [%0], [%1], 16;\n"
                 :: "r"(dst), "l"(src));
}
#define CP_COMMIT() asm volatile("cp.async.commit_group;\n" ::: "memory")

__device__ __forceinline__ float rna_tf32(float v) {
    uint32_t u;
    asm("cvt.rna.tf32.f32 %0, %1;" : "=r"(u) : "f"(v));
    return __uint_as_float(u);
}
__device__ __forceinline__ float fexp2(float x) {
    float y;
    asm("ex2.approx.f32 %0, %1;" : "=f"(y) : "f"(x));
    return y;
}
__device__ __forceinline__ void mma_tf32(float* c, const uint32_t a[4],
                                         const uint32_t b[2]) {
    asm volatile(
        "mma.sync.aligned.m16n8k8.row.col.f32.tf32.tf32.f32 "
        "{%0,%1,%2,%3}, {%4,%5,%6,%7}, {%8,%9}, {%0,%1,%2,%3};"
        : "+f"(c[0]), "+f"(c[1]), "+f"(c[2]), "+f"(c[3])
        : "r"(a[0]), "r"(a[1]), "r"(a[2]), "r"(a[3]), "r"(b[0]), "r"(b[1]));
}
// one x4 ldmatrix: 4 8x8 b16 matrices == one tf32 A-frag OR two tf32 B-frags
__device__ __forceinline__ void ldsm_x4(uint32_t* r, uint32_t addr) {
    asm volatile("ldmatrix.sync.aligned.m8n8.x4.shared.b16 {%0,%1,%2,%3}, [%4];"
        : "=r"(r[0]), "=r"(r[1]), "=r"(r[2]), "=r"(r[3]) : "r"(addr));
}

// ---------------------------------------------------------------------------
// prepass: tf32 rounding + weight transpose(+round)
// ---------------------------------------------------------------------------
__global__ __launch_bounds__(256) void round_tf32_kernel(
    const float* __restrict__ in, float* __restrict__ out)
{
    const size_t i = (size_t)blockIdx.x * 256 + threadIdx.x;
    float4 v = ((const float4*)in)[i];
    v.x = rna_tf32(v.x); v.y = rna_tf32(v.y);
    v.z = rna_tf32(v.z); v.w = rna_tf32(v.w);
    ((float4*)out)[i] = v;
}

__global__ __launch_bounds__(256) void transpose_rna_kernel(
    const float* __restrict__ W, float* __restrict__ Wt, int K, int N)
{
    __shared__ float t[32][33];
    const int n0 = blockIdx.x * 32, k0 = blockIdx.y * 32;
    const int tx = threadIdx.x, ty = threadIdx.y;   // 32 x 8
    #pragma unroll
    for (int i = 0; i < 32; i += 8)
        t[ty + i][tx] = rna_tf32(W[(size_t)(k0 + ty + i) * N + n0 + tx]);
    __syncthreads();
    #pragma unroll
    for (int i = 0; i < 32; i += 8)
        Wt[(size_t)(n0 + ty + i) * K + k0 + tx] = t[tx][ty + i];
}

// ---------------------------------------------------------------------------
// Persistent tf32 mma.sync GEMM: C[M,N] = A[M,K] @ Bt[N,K]^T (+bias)
// BK=32, 3-stage ring, ONE barrier per iter, ldmatrix fragments.
// Each CTA loops over tiles; next-tile prologue overlaps current epilogue.
// ---------------------------------------------------------------------------
#define GSTRIDE 36
#define MAT_BYTES (128 * GSTRIDE * 4)            // 18432
#define STAGE_BYTES (2 * MAT_BYTES)              // 36864
#define GEMM_SMEM (3 * STAGE_BYTES)              // 110592

__global__ __launch_bounds__(256, 2) void tf32_mma_gemm(
    const float* __restrict__ A, const float* __restrict__ Bt,
    const float* __restrict__ bias, float* __restrict__ Cm,
    int M, int N, int K, int round_out)
{
    extern __shared__ float sm[];
    const int tid  = threadIdx.x;
    const int wid  = tid >> 5, lane = tid & 31;
    const int g    = lane >> 2, tg = lane & 3;
    const int mW   = (wid >> 2) * 64;
    const int nW   = (wid & 3) * 32;
    const int NIT = K >> 5;
    const int ntx = N >> 7;
    const int numTiles = (M >> 7) * ntx;

    const uint32_t sb = smem_u32(sm);

    const uint32_t aFragOff =
        (uint32_t)((mW + (lane & 15)) * GSTRIDE + ((lane & 16) ? 4 : 0)) * 4;
    const uint32_t bFragOff = (uint32_t)MAT_BYTES +
        (uint32_t)((nW + (lane & 7) + ((lane & 16) ? 8 : 0)) * GSTRIDE +
                   ((lane & 8) ? 4 : 0)) * 4;

    int t = blockIdx.x;
    if (t >= numTiles) return;

    const float* Ag = A  + (size_t)((t / ntx) << 7) * K;
    const float* Bg = Bt + (size_t)((t % ntx) << 7) * K;

    auto load_stage = [&](const float* Asrc, const float* Bsrc, int s, int kt) {
        const uint32_t base = sb + s * STAGE_BYTES;
        #pragma unroll
        for (int u = 0; u < 4; u++) {
            const int f4 = u * 256 + tid;
            const int r  = f4 >> 3;
            const int c4 = (f4 & 7) << 2;
            const uint32_t off = (uint32_t)(r * GSTRIDE + c4) * 4;
            cp16(base + off,             Asrc + (size_t)r * K + kt + c4);
            cp16(base + MAT_BYTES + off, Bsrc + (size_t)r * K + kt + c4);
        }
    };

    load_stage(Ag, Bg, 0, 0);  CP_COMMIT();
    load_stage(Ag, Bg, 1, 32); CP_COMMIT();

    while (true) {
        float acc[4][4][4];
        #pragma unroll
        for (int mt = 0; mt < 4; mt++)
            #pragma unroll
            for (int nt = 0; nt < 4; nt++)
                #pragma unroll
                for (int e = 0; e < 4; e++) acc[mt][nt][e] = 0.f;

        for (int it = 0; it < NIT; ++it) {
            if (it + 1 < NIT) asm volatile("cp.async.wait_group 1;\n" ::: "memory");
            else              asm volatile("cp.async.wait_group 0;\n" ::: "memory");
            __syncthreads();

            const uint32_t stb = sb + (uint32_t)(it % 3) * STAGE_BYTES;
            #pragma unroll
            for (int kk4 = 0; kk4 < 4; kk4++) {
                const uint32_t kkb = kk4 * 32;      // kk*4 bytes, kk = kk4*8
                uint32_t b01[4], b23[4];
                ldsm_x4(b01, stb + bFragOff + kkb);
                ldsm_x4(b23, stb + bFragOff + 16 * GSTRIDE * 4 + kkb);
                #pragma unroll
                for (int mt = 0; mt < 4; mt++) {
                    uint32_t af[4];
                    ldsm_x4(af, stb + aFragOff + mt * 16 * GSTRIDE * 4 + kkb);
                    mma_tf32(acc[mt][0], af, b01 + 0);
                    mma_tf32(acc[mt][1], af, b01 + 2);
                    mma_tf32(acc[mt][2], af, b23 + 0);
                    mma_tf32(acc[mt][3], af, b23 + 2);
                }
            }

            const int pf = it + 2;
            if (pf < NIT) { load_stage(Ag, Bg, pf % 3, pf * 32); CP_COMMIT(); }
        }

        __syncthreads();   // all frag reads complete before stages are reused

        const int tn = t + gridDim.x;
        const bool more = tn < numTiles;
        if (more) {        // next-tile prologue overlaps current epilogue
            Ag = A  + (size_t)((tn / ntx) << 7) * K;
            Bg = Bt + (size_t)((tn % ntx) << 7) * K;
            load_stage(Ag, Bg, 0, 0);  CP_COMMIT();
            load_stage(Ag, Bg, 1, 32); CP_COMMIT();
        }

        const int rowBase = (t / ntx) << 7, colBase = (t % ntx) << 7;
        #pragma unroll
        for (int mt = 0; mt < 4; mt++) {
            const int r0 = rowBase + mW + mt * 16 + g;
            #pragma unroll
            for (int nt = 0; nt < 4; nt++) {
                const int col = colBase + nW + nt * 8 + 2 * tg;
                float bx = 0.f, by = 0.f;
                if (bias) { bx = bias[col]; by = bias[col + 1]; }
                float2 v0, v1;
                v0.x = acc[mt][nt][0] + bx; v0.y = acc[mt][nt][1] + by;
                v1.x = acc[mt][nt][2] + bx; v1.y = acc[mt][nt][3] + by;
                if (round_out) {
                    v0.x = rna_tf32(v0.x); v0.y = rna_tf32(v0.y);
                    v1.x = rna_tf32(v1.x); v1.y = rna_tf32(v1.y);
                }
                *(float2*)(Cm + (size_t)r0 * N + col)       = v0;
                *(float2*)(Cm + (size_t)(r0 + 8) * N + col) = v1;
            }
        }

        if (!more) return;
        t = tn;
    }
}

// ---------------------------------------------------------------------------
// Tensorized flash attention (R7-best structure; softmax in exp2 domain:
// Q pre-scaled by 0.125*log2e, ex2.approx instead of __expf)
// ---------------------------------------------------------------------------
#define FPAD_K 68
#define FPAD_V 72
#define KBYTES (64 * FPAD_K * 4)                 // 17408
#define VBYTES (64 * FPAD_V * 4)                 // 18432
#define FLASH_SMEM (2 * (KBYTES + VBYTES))       // 71680

__global__ __launch_bounds__(128) void flash_mma_kernel(float* __restrict__ att_out)
{
    extern __shared__ char smc[];
    const uint32_t sb = smem_u32(smc);
    const int tid = threadIdx.x, w = tid >> 5, lane = tid & 31;
    const int g = lane >> 2, tg = lane & 3;
    const int qb = gridDim.x - 1 - blockIdx.x;          // big blocks first
    const int b  = blockIdx.y >> 4, h = blockIdx.y & 15;

    const float* qkvb = g_qkv + (size_t)b * T_ * N1 + (size_t)h * HD_;
    const float* kptr = qkvb + C_;
    const float* vptr = qkvb + 2 * C_;

    // ---- Q fragments in registers, pre-scaled by 0.125*log2e (rna-rounded) ----
    const float qscale = 0.125f * 1.4426950408889634f;
    uint32_t qf[8][4];
    {
        const int r0 = qb * 64 + w * 16 + g;
        const float* p0 = qkvb + (size_t)r0 * N1;
        const float* p1 = p0 + (size_t)8 * N1;
        #pragma unroll
        for (int kk = 0; kk < 8; kk++) {
            qf[kk][0] = __float_as_uint(rna_tf32(qscale * p0[kk * 8 + tg]));
            qf[kk][1] = __float_as_uint(rna_tf32(qscale * p1[kk * 8 + tg]));
            qf[kk][2] = __float_as_uint(rna_tf32(qscale * p0[kk * 8 + tg + 4]));
            qf[kk][3] = __float_as_uint(rna_tf32(qscale * p1[kk * 8 + tg + 4]));
        }
    }

    // ldmatrix base offset for K fragments (bytes, within K tile)
    const uint32_t kFragOff =
        (uint32_t)(((lane & 7) + ((lane & 16) ? 8 : 0)) * FPAD_K +
                   ((lane & 8) ? 4 : 0)) * 4;

    float m0 = -1e30f, m1 = -1e30f, l0 = 0.f, l1 = 0.f;
    float O[8][4];
    #pragma unroll
    for (int d = 0; d < 8; d++)
        #pragma unroll
        for (int e = 0; e < 4; e++) O[d][e] = 0.f;

    auto loadKV = [&](int s, int kb) {
        const uint32_t kb_s = sb + s * (KBYTES + VBYTES);
        const uint32_t vb_s = kb_s + KBYTES;
        #pragma unroll
        for (int i = 0; i < 8; i++) {
            const int idx = tid + i * 128;
            const int r = idx >> 4;
            const int c4 = (idx & 15) << 2;
            const size_t go = (size_t)(kb * 64 + r) * N1 + c4;
            cp16(kb_s + (uint32_t)(r * FPAD_K + c4) * 4, kptr + go);
            cp16(vb_s + (uint32_t)(r * FPAD_V + c4) * 4, vptr + go);
        }
    };

    loadKV(0, 0); CP_COMMIT();

    for (int kb = 0; kb <= qb; ++kb) {
        asm volatile("cp.async.wait_group 0;\n" ::: "memory");
        __syncthreads();
        if (kb < qb) { loadKV((kb + 1) & 1, kb + 1); CP_COMMIT(); }

        const uint32_t kTile = sb + (uint32_t)(kb & 1) * (KBYTES + VBYTES);
        const float* Vs = (const float*)(smc + (size_t)(kb & 1) * (KBYTES + VBYTES)
                                             + KBYTES);

        // ---- S = (Q*c) @ K^T  (log2-domain logits) ----
        float Sf[8][4];
        #pragma unroll
        for (int nt = 0; nt < 8; nt++) {
            Sf[nt][0] = 0.f; Sf[nt][1] = 0.f; Sf[nt][2] = 0.f; Sf[nt][3] = 0.f;
        }
        #pragma unroll
        for (int kk = 0; kk < 8; kk++) {
            uint32_t kf[4][4];
            #pragma unroll
            for (int p = 0; p < 4; p++)
                ldsm_x4(kf[p], kTile + kFragOff +
                                (uint32_t)(p * 16 * FPAD_K + kk * 8) * 4);
            #pragma unroll
            for (int nt = 0; nt < 8; nt++)
                mma_tf32(Sf[nt], qf[kk], kf[nt >> 1] + (nt & 1) * 2);
        }

        // ---- causal mask on diagonal tile ----
        if (kb == qb) {
            const int r0l = w * 16 + g, r1l = r0l + 8;
            #pragma unroll
            for (int nt = 0; nt < 8; nt++) {
                const int c0 = nt * 8 + 2 * tg, c1 = c0 + 1;
                if (c0 > r0l) Sf[nt][0] = -1e30f;
                if (c1 > r0l) Sf[nt][1] = -1e30f;
                if (c0 > r1l) Sf[nt][2] = -1e30f;
                if (c1 > r1l) Sf[nt][3] = -1e30f;
            }
        }

        // ---- online softmax on fragments (exp2 domain) ----
        float mx0 = -1e30f, mx1 = -1e30f;
        #pragma unroll
        for (int nt = 0; nt < 8; nt++) {
            mx0 = fmaxf(mx0, fmaxf(Sf[nt][0], Sf[nt][1]));
            mx1 = fmaxf(mx1, fmaxf(Sf[nt][2], Sf[nt][3]));
        }
        mx0 = fmaxf(mx0, __shfl_xor_sync(0xffffffffu, mx0, 1));
        mx0 = fmaxf(mx0, __shfl_xor_sync(0xffffffffu, mx0, 2));
        mx1 = fmaxf(mx1, __shfl_xor_sync(0xffffffffu, mx1, 1));
        mx1 = fmaxf(mx1, __shfl_xor_sync(0xffffffffu, mx1, 2));
        const float mn0 = fmaxf(m0, mx0), mn1 = fmaxf(m1, mx1);
        const float f0 = fexp2(m0 - mn0), f1 = fexp2(m1 - mn1);
        float s0 = 0.f, s1 = 0.f;
        #pragma unroll
        for (int nt = 0; nt < 8; nt++) {
            Sf[nt][0] = fexp2(Sf[nt][0] - mn0);
            Sf[nt][1] = fexp2(Sf[nt][1] - mn0);
            Sf[nt][2] = fexp2(Sf[nt][2] - mn1);
            Sf[nt][3] = fexp2(Sf[nt][3] - mn1);
            s0 += Sf[nt][0] + Sf[nt][1];
            s1 += Sf[nt][2] + Sf[nt][3];
        }
        s0 += __shfl_xor_sync(0xffffffffu, s0, 1);
        s0 += __shfl_xor_sync(0xffffffffu, s0, 2);
        s1 += __shfl_xor_sync(0xffffffffu, s1, 1);
        s1 += __shfl_xor_sync(0xffffffffu, s1, 2);
        l0 = l0 * f0 + s0;  m0 = mn0;
        l1 = l1 * f1 + s1;  m1 = mn1;
        #pragma unroll
        for (int d = 0; d < 8; d++) {
            O[d][0] *= f0; O[d][1] *= f0;
            O[d][2] *= f1; O[d][3] *= f1;
        }

        // ---- O += P @ V  (P acc-layout -> A-layout via shfl) ----
        const int L0 = (lane & 0x1c) | (tg >> 1);
        const int L1 = L0 + 2;
        const bool odd = (tg & 1);
        #pragma unroll
        for (int nt = 0; nt < 8; nt++) {
            const float p00 = __shfl_sync(0xffffffffu, Sf[nt][0], L0);
            const float p01 = __shfl_sync(0xffffffffu, Sf[nt][1], L0);
            const float p10 = __shfl_sync(0xffffffffu, Sf[nt][2], L0);
            const float p11 = __shfl_sync(0xffffffffu, Sf[nt][3], L0);
            const float r00 = __shfl_sync(0xffffffffu, Sf[nt][0], L1);
            const float r01 = __shfl_sync(0xffffffffu, Sf[nt][1], L1);
            const float r10 = __shfl_sync(0xffffffffu, Sf[nt][2], L1);
            const float r11 = __shfl_sync(0xffffffffu, Sf[nt][3], L1);
            uint32_t aP[4];
            aP[0] = __float_as_uint(rna_tf32(odd ? p01 : p00));
            aP[1] = __float_as_uint(rna_tf32(odd ? p11 : p10));
            aP[2] = __float_as_uint(rna_tf32(odd ? r01 : r00));
            aP[3] = __float_as_uint(rna_tf32(odd ? r11 : r10));
            const float* vp = Vs + (nt * 8 + tg) * FPAD_V + g;
            #pragma unroll
            for (int ntd = 0; ntd < 8; ntd++) {
                uint32_t bf[2];
                bf[0] = __float_as_uint(vp[ntd * 8]);
                bf[1] = __float_as_uint(vp[4 * FPAD_V + ntd * 8]);
                mma_tf32(O[ntd], aP, bf);
            }
        }
        __syncthreads();
    }

    // ---- normalize + store (tf32-rounded for out-proj) ----
    const float inv0 = 1.f / l0, inv1 = 1.f / l1;
    const size_t row0 = (size_t)b * T_ + (size_t)qb * 64 + w * 16 + g;
    const size_t row1 = row0 + 8;
    const int colb = h * HD_ + 2 * tg;
    #pragma unroll
    for (int ntd = 0; ntd < 8; ntd++) {
        float2 v0, v1;
        v0.x = rna_tf32(O[ntd][0] * inv0);
        v0.y = rna_tf32(O[ntd][1] * inv0);
        v1.x = rna_tf32(O[ntd][2] * inv1);
        v1.y = rna_tf32(O[ntd][3] * inv1);
        *(float2*)(att_out + row0 * C_ + colb + ntd * 8) = v0;
        *(float2*)(att_out + row1 * C_ + colb + ntd * 8) = v1;
    }
}

// ---------------------------------------------------------------------------
extern "C" void kernel_launch(void* const* d_in, const int* in_sizes, int n_in,
                              void* d_out, int out_size)
{
    (void)in_sizes; (void)n_in; (void)out_size;
    const float* x    = (const float*)d_in[0];
    const float* Wqkv = (const float*)d_in[2];
    const float* Wout = (const float*)d_in[3];
    const float* bout = (const float*)d_in[4];
    float* out = (float*)d_out;

    float *qkv_p, *att_p, *xr_p, *wt1_p, *wt2_p;
    cudaGetSymbolAddress((void**)&qkv_p, g_qkv);
    cudaGetSymbolAddress((void**)&att_p, g_att);
    cudaGetSymbolAddress((void**)&xr_p,  g_xr);
    cudaGetSymbolAddress((void**)&wt1_p, g_wt1);
    cudaGetSymbolAddress((void**)&wt2_p, g_wt2);

    static bool attr_set = false;
    if (!attr_set) {
        cudaFuncSetAttribute(tf32_mma_gemm,
                             cudaFuncAttributeMaxDynamicSharedMemorySize, GEMM_SMEM);
        cudaFuncSetAttribute(flash_mma_kernel,
                             cudaFuncAttributeMaxDynamicSharedMemorySize, FLASH_SMEM);
        attr_set = true;
    }

    // prepass: round x, transpose+round weights
    round_tf32_kernel<<<(M_ * C_) / 1024, 256>>>(x, xr_p);
    transpose_rna_kernel<<<dim3(N1 / 32, C_ / 32), dim3(32, 8)>>>(Wqkv, wt1_p, C_, N1);
    transpose_rna_kernel<<<dim3(C_ / 32, C_ / 32), dim3(32, 8)>>>(Wout, wt2_p, C_, C_);

    // 1) qkv = x @ Wqkv  (persistent; round output to tf32 for flash)
    tf32_mma_gemm<<<PERSIST_GRID, 256, GEMM_SMEM>>>(
        xr_p, wt1_p, nullptr, qkv_p, M_, N1, C_, 1);

    // 2) tensorized flash attention (R7-best shape, exp2 softmax)
    flash_mma_kernel<<<dim3(T_ / 64, B_ * H_), 128, FLASH_SMEM>>>(att_p);

    // 3) out = att @ Wout + bout  (persistent)
    tf32_mma_gemm<<<PERSIST_GRID, 256, GEMM_SMEM>>>(
        att_p, wt2_p, bout, out, M_, C_, C_, 0);
}

// round 12
// speedup vs baseline: 1.0230x; 1.0230x over previous
#include <cuda_runtime.h>
#include <cstdint>

#define B_  4
#define T_  2048
#define C_  1024
#define H_  16
#define HD_ 64
#define M_  (B_ * T_)     // 8192
#define N1  (3 * C_)      // 3072

// Scratch (__device__ globals per allocation rules)
__device__ float g_qkv[(size_t)M_ * N1];        // 96 MB (tf32-rounded by gemm epilogue)
__device__ float g_att[(size_t)M_ * C_];        // 32 MB (tf32-rounded by flash epilogue)
__device__ float g_xr [(size_t)M_ * C_];        // 32 MB (tf32-rounded x)
__device__ float g_wt1[(size_t)N1 * C_];        // 12 MB (Wqkv^T, rounded)
__device__ float g_wt2[(size_t)C_ * C_];        //  4 MB (Wout^T, rounded)

// ---------------------------------------------------------------------------
// helpers
// ---------------------------------------------------------------------------
__device__ __forceinline__ uint32_t smem_u32(const void* p) {
    uint32_t a;
    asm("{ .reg .u64 t; cvta.to.shared.u64 t, %1; cvt.u32.u64 %0, t; }"
        : "=r"(a) : "l"(p));
    return a;
}
__device__ __forceinline__ void cp16(uint32_t dst, const void* src) {
    asm volatile("cp.async.cg.shared.global [%0], [%1], 16;\n"
                 :: "r"(dst), "l"(src));
}
#define CP_COMMIT() asm volatile("cp.async.commit_group;\n" ::: "memory")

__device__ __forceinline__ float rna_tf32(float v) {
    uint32_t u;
    asm("cvt.rna.tf32.f32 %0, %1;" : "=r"(u) : "f"(v));
    return __uint_as_float(u);
}
__device__ __forceinline__ float fexp2(float x) {
    float y;
    asm("ex2.approx.f32 %0, %1;" : "=f"(y) : "f"(x));
    return y;
}
__device__ __forceinline__ void mma_tf32(float* c, const uint32_t a[4],
                                         const uint32_t b[2]) {
    asm volatile(
        "mma.sync.aligned.m16n8k8.row.col.f32.tf32.tf32.f32 "
        "{%0,%1,%2,%3}, {%4,%5,%6,%7}, {%8,%9}, {%0,%1,%2,%3};"
        : "+f"(c[0]), "+f"(c[1]), "+f"(c[2]), "+f"(c[3])
        : "r"(a[0]), "r"(a[1]), "r"(a[2]), "r"(a[3]), "r"(b[0]), "r"(b[1]));
}
// one x4 ldmatrix: 4 8x8 b16 matrices == one tf32 A-frag OR two tf32 B-frags
__device__ __forceinline__ void ldsm_x4(uint32_t* r, uint32_t addr) {
    asm volatile("ldmatrix.sync.aligned.m8n8.x4.shared.b16 {%0,%1,%2,%3}, [%4];"
        : "=r"(r[0]), "=r"(r[1]), "=r"(r[2]), "=r"(r[3]) : "r"(addr));
}

// ---------------------------------------------------------------------------
// prepass: tf32 rounding + weight transpose(+round)
// ---------------------------------------------------------------------------
__global__ __launch_bounds__(256) void round_tf32_kernel(
    const float* __restrict__ in, float* __restrict__ out)
{
    const size_t i = (size_t)blockIdx.x * 256 + threadIdx.x;
    float4 v = ((const float4*)in)[i];
    v.x = rna_tf32(v.x); v.y = rna_tf32(v.y);
    v.z = rna_tf32(v.z); v.w = rna_tf32(v.w);
    ((float4*)out)[i] = v;
}

__global__ __launch_bounds__(256) void transpose_rna_kernel(
    const float* __restrict__ W, float* __restrict__ Wt, int K, int N)
{
    __shared__ float t[32][33];
    const int n0 = blockIdx.x * 32, k0 = blockIdx.y * 32;
    const int tx = threadIdx.x, ty = threadIdx.y;   // 32 x 8
    #pragma unroll
    for (int i = 0; i < 32; i += 8)
        t[ty + i][tx] = rna_tf32(W[(size_t)(k0 + ty + i) * N + n0 + tx]);
    __syncthreads();
    #pragma unroll
    for (int i = 0; i < 32; i += 8)
        Wt[(size_t)(n0 + ty + i) * K + k0 + tx] = t[tx][ty + i];
}

// ---------------------------------------------------------------------------
// tf32 mma.sync GEMM (EXACT R7 best): C[M,N] = A[M,K] @ Bt[N,K]^T (+bias)
// BK=32, 3-stage ring, ONE barrier per iter, ldmatrix fragments.
// ---------------------------------------------------------------------------
#define GSTRIDE 36
#define MAT_BYTES (128 * GSTRIDE * 4)            // 18432
#define STAGE_BYTES (2 * MAT_BYTES)              // 36864
#define GEMM_SMEM (3 * STAGE_BYTES)              // 110592

__global__ __launch_bounds__(256, 2) void tf32_mma_gemm(
    const float* __restrict__ A, const float* __restrict__ Bt,
    const float* __restrict__ bias, float* __restrict__ Cm,
    int M, int N, int K, int round_out)
{
    extern __shared__ float sm[];
    const int tid  = threadIdx.x;
    const int wid  = tid >> 5, lane = tid & 31;
    const int g    = lane >> 2, tg = lane & 3;
    const int mW   = (wid >> 2) * 64;
    const int nW   = (wid & 3) * 32;
    const int rowBase = blockIdx.y * 128, colBase = blockIdx.x * 128;
    const int NIT = K >> 5;

    const float* Ag = A  + (size_t)rowBase * K;
    const float* Bg = Bt + (size_t)colBase * K;
    const uint32_t sb = smem_u32(sm);

    const uint32_t aFragOff =
        (uint32_t)((mW + (lane & 15)) * GSTRIDE + ((lane & 16) ? 4 : 0)) * 4;
    const uint32_t bFragOff = (uint32_t)MAT_BYTES +
        (uint32_t)((nW + (lane & 7) + ((lane & 16) ? 8 : 0)) * GSTRIDE +
                   ((lane & 8) ? 4 : 0)) * 4;

    auto load_stage = [&](int s, int kt) {
        const uint32_t base = sb + s * STAGE_BYTES;
        #pragma unroll
        for (int u = 0; u < 4; u++) {
            const int f4 = u * 256 + tid;
            const int r  = f4 >> 3;
            const int c4 = (f4 & 7) << 2;
            const uint32_t off = (uint32_t)(r * GSTRIDE + c4) * 4;
            cp16(base + off,             Ag + (size_t)r * K + kt + c4);
            cp16(base + MAT_BYTES + off, Bg + (size_t)r * K + kt + c4);
        }
    };

    float acc[4][4][4];
    #pragma unroll
    for (int mt = 0; mt < 4; mt++)
        #pragma unroll
        for (int nt = 0; nt < 4; nt++)
            #pragma unroll
            for (int e = 0; e < 4; e++) acc[mt][nt][e] = 0.f;

    load_stage(0, 0);  CP_COMMIT();
    load_stage(1, 32); CP_COMMIT();

    for (int it = 0; it < NIT; ++it) {
        if (it + 1 < NIT) asm volatile("cp.async.wait_group 1;\n" ::: "memory");
        else              asm volatile("cp.async.wait_group 0;\n" ::: "memory");
        __syncthreads();

        const uint32_t stb = sb + (uint32_t)(it % 3) * STAGE_BYTES;
        #pragma unroll
        for (int kk4 = 0; kk4 < 4; kk4++) {
            const uint32_t kkb = kk4 * 32;      // kk*4 bytes, kk = kk4*8
            uint32_t b01[4], b23[4];
            ldsm_x4(b01, stb + bFragOff + kkb);
            ldsm_x4(b23, stb + bFragOff + 16 * GSTRIDE * 4 + kkb);
            #pragma unroll
            for (int mt = 0; mt < 4; mt++) {
                uint32_t af[4];
                ldsm_x4(af, stb + aFragOff + mt * 16 * GSTRIDE * 4 + kkb);
                mma_tf32(acc[mt][0], af, b01 + 0);
                mma_tf32(acc[mt][1], af, b01 + 2);
                mma_tf32(acc[mt][2], af, b23 + 0);
                mma_tf32(acc[mt][3], af, b23 + 2);
            }
        }

        const int pf = it + 2;
        if (pf < NIT) { load_stage(pf % 3, pf * 32); CP_COMMIT(); }
    }

    #pragma unroll
    for (int mt = 0; mt < 4; mt++) {
        const int r0 = rowBase + mW + mt * 16 + g;
        #pragma unroll
        for (int nt = 0; nt < 4; nt++) {
            const int col = colBase + nW + nt * 8 + 2 * tg;
            float bx = 0.f, by = 0.f;
            if (bias) { bx = bias[col]; by = bias[col + 1]; }
            float2 v0, v1;
            v0.x = acc[mt][nt][0] + bx; v0.y = acc[mt][nt][1] + by;
            v1.x = acc[mt][nt][2] + bx; v1.y = acc[mt][nt][3] + by;
            if (round_out) {
                v0.x = rna_tf32(v0.x); v0.y = rna_tf32(v0.y);
                v1.x = rna_tf32(v1.x); v1.y = rna_tf32(v1.y);
            }
            *(float2*)(Cm + (size_t)r0 * N + col)       = v0;
            *(float2*)(Cm + (size_t)(r0 + 8) * N + col) = v1;
        }
    }
}

// ---------------------------------------------------------------------------
// Tensorized flash attention (R7 structure + exp2 softmax, single barrier/tile)
// ---------------------------------------------------------------------------
#define FPAD_K 68
#define FPAD_V 72
#define KBYTES (64 * FPAD_K * 4)                 // 17408
#define VBYTES (64 * FPAD_V * 4)                 // 18432
#define FLASH_SMEM (2 * (KBYTES + VBYTES))       // 71680

__global__ __launch_bounds__(128) void flash_mma_kernel(float* __restrict__ att_out)
{
    extern __shared__ char smc[];
    const uint32_t sb = smem_u32(smc);
    const int tid = threadIdx.x, w = tid >> 5, lane = tid & 31;
    const int g = lane >> 2, tg = lane & 3;
    const int qb = gridDim.x - 1 - blockIdx.x;          // big blocks first
    const int b  = blockIdx.y >> 4, h = blockIdx.y & 15;

    const float* qkvb = g_qkv + (size_t)b * T_ * N1 + (size_t)h * HD_;
    const float* kptr = qkvb + C_;
    const float* vptr = qkvb + 2 * C_;

    // ---- Q fragments in registers, pre-scaled by 0.125*log2e (rna-rounded) ----
    const float qscale = 0.125f * 1.4426950408889634f;
    uint32_t qf[8][4];
    {
        const int r0 = qb * 64 + w * 16 + g;
        const float* p0 = qkvb + (size_t)r0 * N1;
        const float* p1 = p0 + (size_t)8 * N1;
        #pragma unroll
        for (int kk = 0; kk < 8; kk++) {
            qf[kk][0] = __float_as_uint(rna_tf32(qscale * p0[kk * 8 + tg]));
            qf[kk][1] = __float_as_uint(rna_tf32(qscale * p1[kk * 8 + tg]));
            qf[kk][2] = __float_as_uint(rna_tf32(qscale * p0[kk * 8 + tg + 4]));
            qf[kk][3] = __float_as_uint(rna_tf32(qscale * p1[kk * 8 + tg + 4]));
        }
    }

    // ldmatrix base offset for K fragments (bytes, within K tile)
    const uint32_t kFragOff =
        (uint32_t)(((lane & 7) + ((lane & 16) ? 8 : 0)) * FPAD_K +
                   ((lane & 8) ? 4 : 0)) * 4;

    float m0 = -1e30f, m1 = -1e30f, l0 = 0.f, l1 = 0.f;
    float O[8][4];
    #pragma unroll
    for (int d = 0; d < 8; d++)
        #pragma unroll
        for (int e = 0; e < 4; e++) O[d][e] = 0.f;

    auto loadKV = [&](int s, int kb) {
        const uint32_t kb_s = sb + s * (KBYTES + VBYTES);
        const uint32_t vb_s = kb_s + KBYTES;
        #pragma unroll
        for (int i = 0; i < 8; i++) {
            const int idx = tid + i * 128;
            const int r = idx >> 4;
            const int c4 = (idx & 15) << 2;
            const size_t go = (size_t)(kb * 64 + r) * N1 + c4;
            cp16(kb_s + (uint32_t)(r * FPAD_K + c4) * 4, kptr + go);
            cp16(vb_s + (uint32_t)(r * FPAD_V + c4) * 4, vptr + go);
        }
    };

    loadKV(0, 0); CP_COMMIT();

    for (int kb = 0; kb <= qb; ++kb) {
        asm volatile("cp.async.wait_group 0;\n" ::: "memory");
        __syncthreads();   // also orders buffer reuse: all warps finished kb-1
        if (kb < qb) { loadKV((kb + 1) & 1, kb + 1); CP_COMMIT(); }

        const uint32_t kTile = sb + (uint32_t)(kb & 1) * (KBYTES + VBYTES);
        const float* Vs = (const float*)(smc + (size_t)(kb & 1) * (KBYTES + VBYTES)
                                             + KBYTES);

        // ---- S = (Q*c) @ K^T  (log2-domain logits) ----
        float Sf[8][4];
        #pragma unroll
        for (int nt = 0; nt < 8; nt++) {
            Sf[nt][0] = 0.f; Sf[nt][1] = 0.f; Sf[nt][2] = 0.f; Sf[nt][3] = 0.f;
        }
        #pragma unroll
        for (int kk = 0; kk < 8; kk++) {
            uint32_t kf[4][4];
            #pragma unroll
            for (int p = 0; p < 4; p++)
                ldsm_x4(kf[p], kTile + kFragOff +
                                (uint32_t)(p * 16 * FPAD_K + kk * 8) * 4);
            #pragma unroll
            for (int nt = 0; nt < 8; nt++)
                mma_tf32(Sf[nt], qf[kk], kf[nt >> 1] + (nt & 1) * 2);
        }

        // ---- causal mask on diagonal tile ----
        if (kb == qb) {
            const int r0l = w * 16 + g, r1l = r0l + 8;
            #pragma unroll
            for (int nt = 0; nt < 8; nt++) {
                const int c0 = nt * 8 + 2 * tg, c1 = c0 + 1;
                if (c0 > r0l) Sf[nt][0] = -1e30f;
                if (c1 > r0l) Sf[nt][1] = -1e30f;
                if (c0 > r1l) Sf[nt][2] = -1e30f;
                if (c1 > r1l) Sf[nt][3] = -1e30f;
            }
        }

        // ---- online softmax on fragments (exp2 domain) ----
        float mx0 = -1e30f, mx1 = -1e30f;
        #pragma unroll
        for (int nt = 0; nt < 8; nt++) {
            mx0 = fmaxf(mx0, fmaxf(Sf[nt][0], Sf[nt][1]));
            mx1 = fmaxf(mx1, fmaxf(Sf[nt][2], Sf[nt][3]));
        }
        mx0 = fmaxf(mx0, __shfl_xor_sync(0xffffffffu, mx0, 1));
        mx0 = fmaxf(mx0, __shfl_xor_sync(0xffffffffu, mx0, 2));
        mx1 = fmaxf(mx1, __shfl_xor_sync(0xffffffffu, mx1, 1));
        mx1 = fmaxf(mx1, __shfl_xor_sync(0xffffffffu, mx1, 2));
        const float mn0 = fmaxf(m0, mx0), mn1 = fmaxf(m1, mx1);
        const float f0 = fexp2(m0 - mn0), f1 = fexp2(m1 - mn1);
        float s0 = 0.f, s1 = 0.f;
        #pragma unroll
        for (int nt = 0; nt < 8; nt++) {
            Sf[nt][0] = fexp2(Sf[nt][0] - mn0);
            Sf[nt][1] = fexp2(Sf[nt][1] - mn0);
            Sf[nt][2] = fexp2(Sf[nt][2] - mn1);
            Sf[nt][3] = fexp2(Sf[nt][3] - mn1);
            s0 += Sf[nt][0] + Sf[nt][1];
            s1 += Sf[nt][2] + Sf[nt][3];
        }
        s0 += __shfl_xor_sync(0xffffffffu, s0, 1);
        s0 += __shfl_xor_sync(0xffffffffu, s0, 2);
        s1 += __shfl_xor_sync(0xffffffffu, s1, 1);
        s1 += __shfl_xor_sync(0xffffffffu, s1, 2);
        l0 = l0 * f0 + s0;  m0 = mn0;
        l1 = l1 * f1 + s1;  m1 = mn1;
        #pragma unroll
        for (int d = 0; d < 8; d++) {
            O[d][0] *= f0; O[d][1] *= f0;
            O[d][2] *= f1; O[d][3] *= f1;
        }

        // ---- O += P @ V  (P acc-layout -> A-layout via shfl) ----
        const int L0 = (lane & 0x1c) | (tg >> 1);
        const int L1 = L0 + 2;
        const bool odd = (tg & 1);
        #pragma unroll
        for (int nt = 0; nt < 8; nt++) {
            const float p00 = __shfl_sync(0xffffffffu, Sf[nt][0], L0);
            const float p01 = __shfl_sync(0xffffffffu, Sf[nt][1], L0);
            const float p10 = __shfl_sync(0xffffffffu, Sf[nt][2], L0);
            const float p11 = __shfl_sync(0xffffffffu, Sf[nt][3], L0);
            const float r00 = __shfl_sync(0xffffffffu, Sf[nt][0], L1);
            const float r01 = __shfl_sync(0xffffffffu, Sf[nt][1], L1);
            const float r10 = __shfl_sync(0xffffffffu, Sf[nt][2], L1);
            const float r11 = __shfl_sync(0xffffffffu, Sf[nt][3], L1);
            uint32_t aP[4];
            aP[0] = __float_as_uint(rna_tf32(odd ? p01 : p00));
            aP[1] = __float_as_uint(rna_tf32(odd ? p11 : p10));
            aP[2] = __float_as_uint(rna_tf32(odd ? r01 : r00));
            aP[3] = __float_as_uint(rna_tf32(odd ? r11 : r10));
            const float* vp = Vs + (nt * 8 + tg) * FPAD_V + g;
            #pragma unroll
            for (int ntd = 0; ntd < 8; ntd++) {
                uint32_t bf[2];
                bf[0] = __float_as_uint(vp[ntd * 8]);
                bf[1] = __float_as_uint(vp[4 * FPAD_V + ntd * 8]);
                mma_tf32(O[ntd], aP, bf);
            }
        }
        // no bottom barrier: next iteration's top barrier provides ordering
    }

    // ---- normalize + store (tf32-rounded for out-proj) ----
    const float inv0 = 1.f / l0, inv1 = 1.f / l1;
    const size_t row0 = (size_t)b * T_ + (size_t)qb * 64 + w * 16 + g;
    const size_t row1 = row0 + 8;
    const int colb = h * HD_ + 2 * tg;
    #pragma unroll
    for (int ntd = 0; ntd < 8; ntd++) {
        float2 v0, v1;
        v0.x = rna_tf32(O[ntd][0] * inv0);
        v0.y = rna_tf32(O[ntd][1] * inv0);
        v1.x = rna_tf32(O[ntd][2] * inv1);
        v1.y = rna_tf32(O[ntd][3] * inv1);
        *(float2*)(att_out + row0 * C_ + colb + ntd * 8) = v0;
        *(float2*)(att_out + row1 * C_ + colb + ntd * 8) = v1;
    }
}

// ---------------------------------------------------------------------------
extern "C" void kernel_launch(void* const* d_in, const int* in_sizes, int n_in,
                              void* d_out, int out_size)
{
    (void)in_sizes; (void)n_in; (void)out_size;
    const float* x    = (const float*)d_in[0];
    const float* Wqkv = (const float*)d_in[2];
    const float* Wout = (const float*)d_in[3];
    const float* bout = (const float*)d_in[4];
    float* out = (float*)d_out;

    float *qkv_p, *att_p, *xr_p, *wt1_p, *wt2_p;
    cudaGetSymbolAddress((void**)&qkv_p, g_qkv);
    cudaGetSymbolAddress((void**)&att_p, g_att);
    cudaGetSymbolAddress((void**)&xr_p,  g_xr);
    cudaGetSymbolAddress((void**)&wt1_p, g_wt1);
    cudaGetSymbolAddress((void**)&wt2_p, g_wt2);

    static bool attr_set = false;
    if (!attr_set) {
        cudaFuncSetAttribute(tf32_mma_gemm,
                             cudaFuncAttributeMaxDynamicSharedMemorySize, GEMM_SMEM);
        cudaFuncSetAttribute(flash_mma_kernel,
                             cudaFuncAttributeMaxDynamicSharedMemorySize, FLASH_SMEM);
        attr_set = true;
    }

    // prepass: round x, transpose+round weights
    round_tf32_kernel<<<(M_ * C_) / 1024, 256>>>(x, xr_p);
    transpose_rna_kernel<<<dim3(N1 / 32, C_ / 32), dim3(32, 8)>>>(Wqkv, wt1_p, C_, N1);
    transpose_rna_kernel<<<dim3(C_ / 32, C_ / 32), dim3(32, 8)>>>(Wout, wt2_p, C_, C_);

    // 1) qkv = x @ Wqkv  (round output to tf32 for flash)
    tf32_mma_gemm<<<dim3(N1 / 128, M_ / 128), 256, GEMM_SMEM>>>(
        xr_p, wt1_p, nullptr, qkv_p, M_, N1, C_, 1);

    // 2) tensorized flash attention (exp2 softmax, single barrier/tile)
    flash_mma_kernel<<<dim3(T_ / 64, B_ * H_), 128, FLASH_SMEM>>>(att_p);

    // 3) out = att @ Wout + bout
    tf32_mma_gemm<<<dim3(C_ / 128, M_ / 128), 256, GEMM_SMEM>>>(
        att_p, wt2_p, bout, out, M_, C_, C_, 0);
}